// round 7
// baseline (speedup 1.0000x reference)
#include <cuda_runtime.h>
#include <cuda_bf16.h>
#include <cuda_pipeline.h>
#include <math.h>
#include <mma.h>

using namespace nvcuda;

// Problem constants (fixed by the dataset)
#define N_NODES 20000
#define CIN     128
#define CH      640
#define COUT    2
#define E_IN    320000
#define EA_MAX  (E_IN + N_NODES)   // edges + self loops = 340000
#define NEG_SLOPE 0.2f
#define M_PAD   (N_NODES + 128)    // GEMM tiles may overrun M; pad activations

// ---------------- scratch (device globals; referenced ONLY from device code) ----
// Activations are kept as split bf16 hi/lo pairs (hi + lo reconstructs to ~2^-18 rel).
__device__ __nv_bfloat16 g_ah[M_PAD * CH];   // activation hi
__device__ __nv_bfloat16 g_al[M_PAD * CH];   // activation lo
__device__ __nv_bfloat16 g_wh[CH * CH];      // current layer weight hi
__device__ __nv_bfloat16 g_wl[CH * CH];      // current layer weight lo
__device__ float g_hw[M_PAD * CH];     // hW = h @ W (fp32, padded)
__device__ float g_as[N_NODES];        // per-node alpha_src = hW . a_src
__device__ float g_ad[N_NODES];        // per-node alpha_dst = hW . a_dst
__device__ int   g_off [N_NODES + 1];  // CSR offsets by dst
__device__ int   g_fill[N_NODES];      // degree counter / fill pointer
__device__ int   g_srcs[EA_MAX];       // src node per CSR slot
__device__ int   g_is64;               // 1 if edge_index is int64, 0 if int32

// ---------------- edge_index dtype detection ----------------
__global__ void k_detect(const int* __restrict__ ei32) {
    __shared__ int nz;
    if (threadIdx.x == 0) nz = 0;
    __syncthreads();
    for (int i = threadIdx.x; i < 1024; i += blockDim.x)
        if (ei32[2 * i + 1] != 0) nz = 1;
    __syncthreads();
    if (threadIdx.x == 0) g_is64 = (nz == 0) ? 1 : 0;
}

__device__ __forceinline__ int edge_at(const void* ei, int idx) {
    return g_is64 ? (int)((const long long*)ei)[idx]
                  : ((const int*)ei)[idx];
}

// ---------------- CSR build (dst-sorted edge list) ----------------
__global__ void k_zero() {
    int i = blockIdx.x * blockDim.x + threadIdx.x;
    if (i < N_NODES) g_fill[i] = 0;
}

__global__ void k_count(const void* __restrict__ ei, int E, int EA) {
    int j = blockIdx.x * blockDim.x + threadIdx.x;
    if (j >= EA) return;
    int dst = (j < E) ? edge_at(ei, E + j) : (j - E);
    if (dst < 0 || dst >= N_NODES) return;
    atomicAdd(&g_fill[dst], 1);
}

__global__ void k_scan() {   // exclusive scan of g_fill -> g_off, single block of 1024
    __shared__ int part[1024];
    const int n = N_NODES;
    int t = threadIdx.x;
    const int chunk = (n + 1023) / 1024;
    int base = t * chunk;
    int s = 0;
    for (int i = 0; i < chunk; i++) {
        int idx = base + i;
        if (idx < n) s += g_fill[idx];
    }
    part[t] = s;
    __syncthreads();
    for (int o = 1; o < 1024; o <<= 1) {
        int v = (t >= o) ? part[t - o] : 0;
        __syncthreads();
        part[t] += v;
        __syncthreads();
    }
    int run = (t == 0) ? 0 : part[t - 1];
    for (int i = 0; i < chunk; i++) {
        int idx = base + i;
        if (idx < n) { int d = g_fill[idx]; g_off[idx] = run; run += d; }
    }
    if (t == 1023) g_off[n] = part[1023];
}

__global__ void k_copy() {
    int i = blockIdx.x * blockDim.x + threadIdx.x;
    if (i < N_NODES) g_fill[i] = g_off[i];
}

__global__ void k_fill(const void* __restrict__ ei, int E, int EA) {
    int j = blockIdx.x * blockDim.x + threadIdx.x;
    if (j >= EA) return;
    int src = (j < E) ? edge_at(ei, j)     : (j - E);
    int dst = (j < E) ? edge_at(ei, E + j) : (j - E);
    if (dst < 0 || dst >= N_NODES) return;
    if (src < 0 || src >= N_NODES) src = 0;
    int pos = atomicAdd(&g_fill[dst], 1);
    if (pos >= 0 && pos < EA_MAX) g_srcs[pos] = src;
}

// ---------------- split helpers ----------------
__device__ __forceinline__ void split_bf(float v, __nv_bfloat16& h, __nv_bfloat16& l) {
    h = __float2bfloat16(v);
    l = __float2bfloat16(v - __bfloat162float(h));
}

// x [N_NODES,128] -> g_ah/g_al [M_PAD,128], pad rows zeroed
__global__ void k_split_x(const float* __restrict__ x) {
    int i = blockIdx.x * blockDim.x + threadIdx.x;
    if (i >= M_PAD * CIN) return;
    float v = (i < N_NODES * CIN) ? x[i] : 0.f;
    split_bf(v, g_ah[i], g_al[i]);
}

// W [K,640] -> g_wh/g_wl
__global__ void k_split_w(const float* __restrict__ W, int n) {
    int i = blockIdx.x * blockDim.x + threadIdx.x;
    if (i >= n) return;
    split_bf(W[i], g_wh[i], g_wl[i]);
}

// ---------------- bf16x3 split-precision tensor GEMM (pre-split operands) -----
// g_hw[M_PAD,CH] = (Ah+Al)[.,K] @ (Wh+Wl)[K,CH], dropping the lo*lo term.
// BM=128, BN=128, BK=16, 256 threads (8 warps: 4m x 2n), warp tile 32x64,
// double-buffered cp.async staging, wmma m16n16k16 bf16, fp32 accum.
#define BMT 128
#define BNT 128
#define BKT 16
#define LDA 24    // 16 + 8 pad (48B rows, 16B-aligned)
#define LDB 136   // 128 + 8 pad (272B rows, 16B-aligned)

__global__ __launch_bounds__(256) void gemm_bf(int K)
{
    __shared__ __align__(16) __nv_bfloat16 sAh[2][BMT][LDA];
    __shared__ __align__(16) __nv_bfloat16 sAl[2][BMT][LDA];
    __shared__ __align__(16) __nv_bfloat16 sBh[2][BKT][LDB];
    __shared__ __align__(16) __nv_bfloat16 sBl[2][BKT][LDB];

    int t = threadIdx.x;
    int bm = blockIdx.y * BMT, bn = blockIdx.x * BNT;
    int warp = t >> 5;
    int wm = (warp & 3) * 32;    // warp m offset (4 warps over 128 rows)
    int wn = (warp >> 2) * 64;   // warp n offset (2 warps over 128 cols)

    // copy assignments: A per stage per array = 256 x 16B chunks (2/row)
    int arow = t >> 1,  ac8 = (t & 1) << 3;
    // B per stage per array = 256 x 16B chunks (16/row)
    int brow = t >> 4,  bc8 = (t & 15) << 3;

    wmma::fragment<wmma::accumulator, 16, 16, 16, float> acc[2][4];
#pragma unroll
    for (int i = 0; i < 2; i++)
#pragma unroll
        for (int j = 0; j < 4; j++)
            wmma::fill_fragment(acc[i][j], 0.0f);

#define LOAD_STAGE(s, k0)                                                                     \
    do {                                                                                      \
        __pipeline_memcpy_async(&sAh[s][arow][ac8],                                           \
            g_ah + (size_t)(bm + arow) * K + (k0) + ac8, 16);                                 \
        __pipeline_memcpy_async(&sAl[s][arow][ac8],                                           \
            g_al + (size_t)(bm + arow) * K + (k0) + ac8, 16);                                 \
        __pipeline_memcpy_async(&sBh[s][brow][bc8],                                           \
            g_wh + (size_t)((k0) + brow) * CH + bn + bc8, 16);                                \
        __pipeline_memcpy_async(&sBl[s][brow][bc8],                                           \
            g_wl + (size_t)((k0) + brow) * CH + bn + bc8, 16);                                \
    } while (0)

    LOAD_STAGE(0, 0);
    __pipeline_commit();

    int nk = K / BKT;
    for (int ks = 0; ks < nk; ks++) {
        if (ks + 1 < nk) {
            LOAD_STAGE((ks + 1) & 1, (ks + 1) * BKT);
            __pipeline_commit();
            __pipeline_wait_prior(1);
        } else {
            __pipeline_wait_prior(0);
        }
        __syncthreads();
        int s = ks & 1;

        wmma::fragment<wmma::matrix_a, 16, 16, 16, __nv_bfloat16, wmma::row_major> ah[2], al[2];
        wmma::fragment<wmma::matrix_b, 16, 16, 16, __nv_bfloat16, wmma::row_major> bh[4], bl[4];
#pragma unroll
        for (int i = 0; i < 2; i++) {
            wmma::load_matrix_sync(ah[i], &sAh[s][wm + i * 16][0], LDA);
            wmma::load_matrix_sync(al[i], &sAl[s][wm + i * 16][0], LDA);
        }
#pragma unroll
        for (int j = 0; j < 4; j++) {
            wmma::load_matrix_sync(bh[j], &sBh[s][0][wn + j * 16], LDB);
            wmma::load_matrix_sync(bl[j], &sBl[s][0][wn + j * 16], LDB);
        }
#pragma unroll
        for (int i = 0; i < 2; i++)
#pragma unroll
            for (int j = 0; j < 4; j++) {
                wmma::mma_sync(acc[i][j], ah[i], bh[j], acc[i][j]);
                wmma::mma_sync(acc[i][j], ah[i], bl[j], acc[i][j]);
                wmma::mma_sync(acc[i][j], al[i], bh[j], acc[i][j]);
            }
        __syncthreads();
    }

    // store (g_hw is padded; rows >= N_NODES are scratch)
#pragma unroll
    for (int i = 0; i < 2; i++)
#pragma unroll
        for (int j = 0; j < 4; j++)
            wmma::store_matrix_sync(
                g_hw + (size_t)(bm + wm + i * 16) * CH + bn + wn + j * 16,
                acc[i][j], CH, wmma::mem_row_major);
}

// ---------------- per-node attention logits (warp per node, reads g_hw) -------
__global__ void k_alphas(const float* __restrict__ a_s,
                         const float* __restrict__ a_d)
{
    int gw = (blockIdx.x * blockDim.x + threadIdx.x) >> 5;
    int lane = threadIdx.x & 31;
    if (gw >= N_NODES) return;
    const float* row = g_hw + (size_t)gw * CH;
    float s = 0.f, d = 0.f;
    for (int c = lane; c < CH; c += 32) {
        float v = row[c];
        s = fmaf(v, a_s[c], s);
        d = fmaf(v, a_d[c], d);
    }
#pragma unroll
    for (int o = 16; o; o >>= 1) {
        s += __shfl_down_sync(0xffffffffu, s, o);
        d += __shfl_down_sync(0xffffffffu, d, o);
    }
    if (lane == 0) { g_as[gw] = s; g_ad[gw] = d; }
}

// ---------------- layer 5 projection + logits (warp per node, Co=2) -----------
// reads split activations hi+lo
__global__ void k_layer5(const float* __restrict__ W,
                         const float* __restrict__ a_s,
                         const float* __restrict__ a_d)
{
    int gw = (blockIdx.x * blockDim.x + threadIdx.x) >> 5;
    int lane = threadIdx.x & 31;
    if (gw >= N_NODES) return;
    const __nv_bfloat16* rh = g_ah + (size_t)gw * CH;
    const __nv_bfloat16* rl = g_al + (size_t)gw * CH;
    float c0 = 0.f, c1 = 0.f;
    for (int k = lane; k < CH; k += 32) {
        float v = __bfloat162float(rh[k]) + __bfloat162float(rl[k]);
        c0 = fmaf(v, W[2 * k + 0], c0);
        c1 = fmaf(v, W[2 * k + 1], c1);
    }
#pragma unroll
    for (int o = 16; o; o >>= 1) {
        c0 += __shfl_down_sync(0xffffffffu, c0, o);
        c1 += __shfl_down_sync(0xffffffffu, c1, o);
    }
    if (lane == 0) {
        g_hw[2 * gw + 0] = c0;
        g_hw[2 * gw + 1] = c1;
        g_as[gw] = c0 * a_s[0] + c1 * a_s[1];
        g_ad[gw] = c0 * a_d[0] + c1 * a_d[1];
    }
}

// ---------------- softmax-attention aggregation (block per dst node) ----------
// Internal layers: writes relu(result) as split bf16 hi/lo into g_ah/g_al.
// Final layer: writes fp32 into out_ext (Co=2, no relu).
__device__ __forceinline__ float leaky(float x) {
    return x > 0.f ? x : NEG_SLOPE * x;
}

__global__ __launch_bounds__(128) void k_aggregate(
    const float* __restrict__ bias, float* __restrict__ out_ext,
    int use_ext_out, int Co)
{
    int i = blockIdx.x;
    int t = threadIdx.x;           // 128 threads
    int s0 = g_off[i], s1 = g_off[i + 1];
    float adi = g_ad[i];
    __shared__ float red[128];
    __shared__ float sw[128];
    __shared__ int   ssrc[128];

    // pass 1: max logit
    float mx = -1e30f;
    for (int j = s0 + t; j < s1; j += 128)
        mx = fmaxf(mx, leaky(g_as[g_srcs[j]] + adi));
    red[t] = mx; __syncthreads();
    for (int o = 64; o; o >>= 1) {
        if (t < o) red[t] = fmaxf(red[t], red[t + o]);
        __syncthreads();
    }
    mx = red[0]; __syncthreads();

    // pass 2: sum of exp
    float sm = 0.f;
    for (int j = s0 + t; j < s1; j += 128)
        sm += __expf(leaky(g_as[g_srcs[j]] + adi) - mx);
    red[t] = sm; __syncthreads();
    for (int o = 64; o; o >>= 1) {
        if (t < o) red[t] += red[t + o];
        __syncthreads();
    }
    float inv = 1.f / red[0];
    __syncthreads();

    // pass 3: stage per-edge weights in shared (one exp per edge), then
    // all threads walk the chunk; each thread owns up to 5 columns.
    float acc[5] = {0.f, 0.f, 0.f, 0.f, 0.f};
    for (int base = s0; base < s1; base += 128) {
        int j = base + t;
        if (j < s1) {
            int s = g_srcs[j];
            ssrc[t] = s;
            sw[t]   = __expf(leaky(g_as[s] + adi) - mx) * inv;
        }
        __syncthreads();
        int cnt = min(128, s1 - base);
        for (int jj = 0; jj < cnt; jj++) {
            float w = sw[jj];
            const float* row = g_hw + (size_t)ssrc[jj] * Co;
#pragma unroll
            for (int k = 0; k < 5; k++) {
                int c = t + k * 128;
                if (c < Co) acc[k] = fmaf(w, row[c], acc[k]);
            }
        }
        __syncthreads();
    }

    if (use_ext_out) {
#pragma unroll
        for (int k = 0; k < 5; k++) {
            int c = t + k * 128;
            if (c < Co) out_ext[(size_t)i * Co + c] = acc[k] + bias[c];
        }
    } else {
#pragma unroll
        for (int k = 0; k < 5; k++) {
            int c = t + k * 128;
            if (c < Co) {
                float v = fmaxf(acc[k] + bias[c], 0.f);
                __nv_bfloat16 h, l;
                split_bf(v, h, l);
                g_ah[(size_t)i * CH + c] = h;
                g_al[(size_t)i * CH + c] = l;
            }
        }
    }
}

// ---------------- launch (kernel launches ONLY; no other CUDA API) ------------
extern "C" void kernel_launch(void* const* d_in, const int* in_sizes, int n_in,
                              void* d_out, int out_size)
{
    const float* x  = (const float*)d_in[0];
    const void*  ei = d_in[1];
    const float* W[5]  = {(const float*)d_in[2],  (const float*)d_in[6],
                          (const float*)d_in[10], (const float*)d_in[14],
                          (const float*)d_in[18]};
    const float* As[5] = {(const float*)d_in[3],  (const float*)d_in[7],
                          (const float*)d_in[11], (const float*)d_in[15],
                          (const float*)d_in[19]};
    const float* Ad[5] = {(const float*)d_in[4],  (const float*)d_in[8],
                          (const float*)d_in[12], (const float*)d_in[16],
                          (const float*)d_in[20]};
    const float* Bv[5] = {(const float*)d_in[5],  (const float*)d_in[9],
                          (const float*)d_in[13], (const float*)d_in[17],
                          (const float*)d_in[21]};

    int E  = in_sizes[1] / 2;     // 320000
    int EA = E + N_NODES;         // 340000

    // --- dtype detect + CSR build (topology identical across layers) ---
    k_detect<<<1, 256>>>((const int*)ei);
    k_zero <<<(N_NODES + 255) / 256, 256>>>();
    k_count<<<(EA + 255) / 256, 256>>>(ei, E, EA);
    k_scan <<<1, 1024>>>();
    k_copy <<<(N_NODES + 255) / 256, 256>>>();
    k_fill <<<(EA + 255) / 256, 256>>>(ei, E, EA);

    dim3 ggrid(CH / BNT, (N_NODES + BMT - 1) / BMT);  // (5, 157)
    int  awarps = (N_NODES * 32 + 255) / 256;         // 2500 blocks of 256

    // --- layer 1 (Ci=128) ---
    k_split_x<<<(M_PAD * CIN + 255) / 256, 256>>>(x);
    k_split_w<<<(CIN * CH + 255) / 256, 256>>>(W[0], CIN * CH);
    gemm_bf<<<ggrid, 256>>>(CIN);
    k_alphas<<<awarps, 256>>>(As[0], Ad[0]);
    k_aggregate<<<N_NODES, 128>>>(Bv[0], nullptr, 0, CH);

    // --- layers 2..4 (Ci=640) ---
    for (int l = 1; l < 4; l++) {
        k_split_w<<<(CH * CH + 255) / 256, 256>>>(W[l], CH * CH);
        gemm_bf<<<ggrid, 256>>>(CH);
        k_alphas<<<awarps, 256>>>(As[l], Ad[l]);
        k_aggregate<<<N_NODES, 128>>>(Bv[l], nullptr, 0, CH);
    }

    // --- layer 5 (Co=2, no relu) ---
    k_layer5<<<awarps, 256>>>(W[4], As[4], Ad[4]);
    k_aggregate<<<N_NODES, 128>>>(Bv[4], (float*)d_out, 1, COUT);
}